// round 3
// baseline (speedup 1.0000x reference)
#include <cuda_runtime.h>
#include <cuda_fp16.h>

#define MAXN 100000
#define MAXE 1600000
typedef unsigned long long u64;

// ---------------- scratch (device globals; allocation-free) ----------------
__device__ __align__(16) __half g_h1h[MAXN * 128];  // layer1 features (fp16, gather-only)
__device__ __align__(16) float g_z1[MAXN * 128];    // layer1 output z = elu(agg + b1)
__device__ __align__(16) float g_h2[MAXN * 64];     // layer2 features h2 = z@W2 (fp32)
__device__ __align__(16) float g_z2[MAXN * 64];     // layer2 output z2
__device__ __align__(8) float g_as1[MAXN * 2];
__device__ __align__(8) float g_ad1[MAXN * 2];
__device__ float g_as2[MAXN];
__device__ float g_ad2[MAXN];
__device__ int g_deg[MAXN];
__device__ int g_rowstart[MAXN + 1];
__device__ int g_cursor[MAXN];
__device__ int g_part[128];
__device__ int g_csr_src[MAXE + MAXN];

// ---------------- f32x2 packed helpers ----------------
__device__ __forceinline__ u64 pack2(float lo, float hi) {
    u64 r;
    asm("mov.b64 %0, {%1, %2};" : "=l"(r) : "f"(lo), "f"(hi));
    return r;
}
__device__ __forceinline__ void unpack2(u64 v, float& lo, float& hi) {
    asm("mov.b64 {%0, %1}, %2;" : "=f"(lo), "=f"(hi) : "l"(v));
}
__device__ __forceinline__ void fma2(u64& d, u64 a, u64 b) {
    asm("fma.rn.f32x2 %0, %1, %2, %0;" : "+l"(d) : "l"(a), "l"(b));
}

// ---------------- CSR build ----------------
__global__ void zero_deg_kernel(int N) {
    int i = blockIdx.x * blockDim.x + threadIdx.x;
    if (i < N) g_deg[i] = 0;
}

__global__ void hist_kernel(const int* __restrict__ edst, int E, int N) {
    int t = blockIdx.x * blockDim.x + threadIdx.x;
    if (t >= E + N) return;
    int dst = (t < E) ? edst[t] : (t - E);
    atomicAdd(&g_deg[dst], 1);
}

__global__ void scan1_kernel(int N) {
    __shared__ int sm[1024];
    int i = blockIdx.x * 1024 + threadIdx.x;
    int v = (i < N) ? g_deg[i] : 0;
    sm[threadIdx.x] = v;
    __syncthreads();
#pragma unroll
    for (int o = 1; o < 1024; o <<= 1) {
        int t = 0;
        if (threadIdx.x >= o) t = sm[threadIdx.x - o];
        __syncthreads();
        if (threadIdx.x >= o) sm[threadIdx.x] += t;
        __syncthreads();
    }
    if (i < N) g_rowstart[i] = sm[threadIdx.x] - v;  // exclusive within block
    if (threadIdx.x == 1023) g_part[blockIdx.x] = sm[1023];
}

// parallel exclusive scan of block partials (nb <= 128)
__global__ void scan2_kernel(int nb) {
    __shared__ int sm[128];
    int v = (threadIdx.x < nb) ? g_part[threadIdx.x] : 0;
    sm[threadIdx.x] = v;
    __syncthreads();
#pragma unroll
    for (int o = 1; o < 128; o <<= 1) {
        int t = 0;
        if (threadIdx.x >= o) t = sm[threadIdx.x - o];
        __syncthreads();
        if (threadIdx.x >= o) sm[threadIdx.x] += t;
        __syncthreads();
    }
    if (threadIdx.x < nb) g_part[threadIdx.x] = sm[threadIdx.x] - v;
}

__global__ void scan3_kernel(int N, int total) {
    int i = blockIdx.x * blockDim.x + threadIdx.x;
    if (i < N) {
        int v = g_rowstart[i] + g_part[i >> 10];
        g_rowstart[i] = v;
        g_cursor[i] = v;
    }
    if (i == 0) g_rowstart[N] = total;
}

// scatter edges into CSR order (index permutation only)
__global__ void scatter_kernel(const int* __restrict__ esrc, const int* __restrict__ edst,
                               int E, int N) {
    int t = blockIdx.x * blockDim.x + threadIdx.x;
    if (t >= E + N) return;
    int src, dst;
    if (t < E) { src = esrc[t]; dst = edst[t]; }
    else       { src = dst = t - E; }
    int pos = atomicAdd(&g_cursor[dst], 1);
    g_csr_src[pos] = src;
}

// ------- fused GEMM + alpha: Y = X@W; as/ad = (Y*a_src).sum / (Y*a_dst).sum -------
// NC=128 -> Y stored fp16 (g_h1h), 2 heads. NC=64 -> Y fp32, 1 head.
template <int NC>
__global__ void gemm_alpha_kernel(const float* __restrict__ X, const float* __restrict__ W,
                                  void* __restrict__ Yout,
                                  const float* __restrict__ av_s, const float* __restrict__ av_d,
                                  float* __restrict__ out_s, float* __restrict__ out_d, int N) {
    extern __shared__ float smem[];
    float* Xs = smem;               // 128 x 128
    float* Ws = smem + 128 * 128;   // 128 x NC
    const int tid = threadIdx.x;
    const int row0 = blockIdx.x * 128;
    constexpr int NH = (NC == 128) ? 2 : 1;

    for (int i = tid * 4; i < 128 * NC; i += 256 * 4)
        *(float4*)&Ws[i] = *(const float4*)&W[i];
    for (int i = tid * 4; i < 128 * 128; i += 256 * 4) {
        int gr = row0 + (i >> 7);
        float4 v = make_float4(0.f, 0.f, 0.f, 0.f);
        if (gr < N) v = *(const float4*)&X[gr * 128 + (i & 127)];
        *(float4*)&Xs[i] = v;
    }
    __syncthreads();

    constexpr int MC = NC / 16;   // 8 or 4
    constexpr int MH = MC / 2;
    const int tx = tid & 15, ty = tid >> 4;
    const int r0 = ty * 8, c0 = tx * MC;
    u64 acc[8][MH];
#pragma unroll
    for (int i = 0; i < 8; i++)
#pragma unroll
        for (int j = 0; j < MH; j++) acc[i][j] = pack2(0.f, 0.f);

#pragma unroll 4
    for (int k = 0; k < 128; k++) {
        float bb[MC];
#pragma unroll
        for (int j4 = 0; j4 < MC; j4 += 4)
            *(float4*)&bb[j4] = *(const float4*)&Ws[k * NC + c0 + j4];
        u64 bp[MH];
#pragma unroll
        for (int j = 0; j < MH; j++) bp[j] = pack2(bb[2 * j], bb[2 * j + 1]);
#pragma unroll
        for (int i = 0; i < 8; i++) {
            float a = Xs[(r0 + i) * 128 + k];
            u64 ap = pack2(a, a);
#pragma unroll
            for (int j = 0; j < MH; j++) fma2(acc[i][j], ap, bp[j]);
        }
    }

    // unpack accumulators
    float o[8][MC];
#pragma unroll
    for (int i = 0; i < 8; i++)
#pragma unroll
        for (int j = 0; j < MH; j++) unpack2(acc[i][j], o[i][2 * j], o[i][2 * j + 1]);

    // write Y
#pragma unroll
    for (int i = 0; i < 8; i++) {
        int gr = row0 + r0 + i;
        if (gr < N) {
            if (NC == 128) {
                __half hb[8];
#pragma unroll
                for (int j = 0; j < MC; j++) hb[j] = __float2half_rn(o[i][j]);
                *(uint4*)((__half*)Yout + (size_t)gr * 128 + c0) = *(uint4*)hb;
            } else {
#pragma unroll
                for (int j4 = 0; j4 < MC; j4 += 4)
                    *(float4*)((float*)Yout + (size_t)gr * 64 + c0 + j4) = *(float4*)&o[i][j4];
            }
        }
    }

    // alpha partial dots: av vectors are flat [NC] (== [H*64] with global col index)
    float avs[MC], avd[MC];
#pragma unroll
    for (int j = 0; j < MC; j++) { avs[j] = av_s[c0 + j]; avd[j] = av_d[c0 + j]; }

    __syncthreads();  // done with Xs/Ws; reuse smem for alpha reduce
    float* sS = smem;
    float* sD = smem + 128 * NH;
    if (tid < 128 * NH) { sS[tid] = 0.f; sD[tid] = 0.f; }
    __syncthreads();

    const int head = (NC == 128) ? (tx >> 3) : 0;
#pragma unroll
    for (int i = 0; i < 8; i++) {
        float ps = 0.f, pd = 0.f;
#pragma unroll
        for (int j = 0; j < MC; j++) {
            ps = fmaf(o[i][j], avs[j], ps);
            pd = fmaf(o[i][j], avd[j], pd);
        }
        int li = (r0 + i) * NH + head;
        atomicAdd(&sS[li], ps);
        atomicAdd(&sD[li], pd);
    }
    __syncthreads();
    if (tid < 128 * NH) {
        int gr = row0 + tid / NH;
        if (gr < N) {
            out_s[row0 * NH + tid] = sS[tid];
            out_d[row0 * NH + tid] = sD[tid];
        }
    }
}

// ---------------- layer1 aggregate: warp/dst, inline ee, fp16 gather, fused bias+elu ----------------
__global__ void agg1_kernel(const float* __restrict__ b1, int N) {
    int w = blockIdx.x * 8 + (threadIdx.x >> 5);
    int lane = threadIdx.x & 31;
    if (w >= N) return;
    int s0 = g_rowstart[w], s1 = g_rowstart[w + 1];
    float2 ad = *(const float2*)&g_ad1[w * 2];
    const int head = lane >> 4;  // feats 0..63 = head0, 64..127 = head1
    float4 acc = make_float4(0.f, 0.f, 0.f, 0.f);
    float den0 = 0.f, den1 = 0.f;

    for (int base = s0; base < s1; base += 32) {
        int e = base + lane;
        int msrc = 0;
        float me0 = 0.f, me1 = 0.f;
        if (e < s1) {
            msrc = g_csr_src[e];
            float2 as = *(const float2*)&g_as1[msrc * 2];
            float v0 = as.x + ad.x, v1 = as.y + ad.y;
            v0 = v0 > 0.f ? v0 : 0.2f * v0;
            v1 = v1 > 0.f ? v1 : 0.2f * v1;
            me0 = __expf(v0);
            me1 = __expf(v1);
        }
        den0 += me0;
        den1 += me1;
        int cnt = min(32, s1 - base);
        for (int j = 0; j < cnt; j++) {
            int s = __shfl_sync(0xffffffffu, msrc, j);
            float a0 = __shfl_sync(0xffffffffu, me0, j);
            float a1 = __shfl_sync(0xffffffffu, me1, j);
            float a = head ? a1 : a0;
            uint2 u = ((const uint2*)(g_h1h + (size_t)s * 128))[lane];
            __half2* ph = (__half2*)&u;
            float2 f0 = __half22float2(ph[0]);
            float2 f1 = __half22float2(ph[1]);
            acc.x = fmaf(a, f0.x, acc.x);
            acc.y = fmaf(a, f0.y, acc.y);
            acc.z = fmaf(a, f1.x, acc.z);
            acc.w = fmaf(a, f1.y, acc.w);
        }
    }
#pragma unroll
    for (int o = 16; o; o >>= 1) {
        den0 += __shfl_xor_sync(0xffffffffu, den0, o);
        den1 += __shfl_xor_sync(0xffffffffu, den1, o);
    }
    float rden = 1.f / (head ? den1 : den0);
    float4 b = *(const float4*)&b1[lane * 4];
    float4 r;
    r.x = acc.x * rden + b.x;
    r.y = acc.y * rden + b.y;
    r.z = acc.z * rden + b.z;
    r.w = acc.w * rden + b.w;
    r.x = r.x > 0.f ? r.x : (__expf(r.x) - 1.f);
    r.y = r.y > 0.f ? r.y : (__expf(r.y) - 1.f);
    r.z = r.z > 0.f ? r.z : (__expf(r.z) - 1.f);
    r.w = r.w > 0.f ? r.w : (__expf(r.w) - 1.f);
    *(float4*)&g_z1[w * 128 + lane * 4] = r;
}

// ---------------- layer2 aggregate: warp/dst, inline ee, fp32 gather, fused bias ----------------
__global__ void agg2_kernel(const float* __restrict__ b2, int N) {
    int w = blockIdx.x * 8 + (threadIdx.x >> 5);
    int lane = threadIdx.x & 31;
    if (w >= N) return;
    int s0 = g_rowstart[w], s1 = g_rowstart[w + 1];
    float add_d = g_ad2[w];
    float2 acc = make_float2(0.f, 0.f);
    float den = 0.f;

    for (int base = s0; base < s1; base += 32) {
        int e = base + lane;
        int msrc = 0;
        float mee = 0.f;
        if (e < s1) {
            msrc = g_csr_src[e];
            float v = g_as2[msrc] + add_d;
            v = v > 0.f ? v : 0.2f * v;
            mee = __expf(v);
        }
        den += mee;
        int cnt = min(32, s1 - base);
        for (int j = 0; j < cnt; j++) {
            int s = __shfl_sync(0xffffffffu, msrc, j);
            float a = __shfl_sync(0xffffffffu, mee, j);
            float2 v = *(const float2*)&g_h2[(size_t)s * 64 + lane * 2];
            acc.x = fmaf(a, v.x, acc.x);
            acc.y = fmaf(a, v.y, acc.y);
        }
    }
#pragma unroll
    for (int o = 16; o; o >>= 1) den += __shfl_xor_sync(0xffffffffu, den, o);
    float rden = 1.f / den;
    float2 b = *(const float2*)&b2[lane * 2];
    float2 r;
    r.x = acc.x * rden + b.x;
    r.y = acc.y * rden + b.y;
    *(float2*)&g_z2[w * 64 + lane * 2] = r;
}

// ---------------- decode: dot(z2[a], z2[b]) over 64 ----------------
__global__ void decode_kernel(const int* __restrict__ eli, int EL, float* __restrict__ out) {
    int t = blockIdx.x * blockDim.x + threadIdx.x;
    int g = t >> 4, li = t & 15;
    if (g >= EL) return;
    int a = eli[g];
    int b = eli[EL + g];
    float4 va = *(const float4*)&g_z2[(size_t)a * 64 + li * 4];
    float4 vb = *(const float4*)&g_z2[(size_t)b * 64 + li * 4];
    float s = va.x * vb.x + va.y * vb.y + va.z * vb.z + va.w * vb.w;
#pragma unroll
    for (int o = 8; o; o >>= 1) s += __shfl_down_sync(0xffffffffu, s, o, 16);
    if (li == 0) out[g] = s;
}

// ---------------- launcher ----------------
extern "C" void kernel_launch(void* const* d_in, const int* in_sizes, int n_in,
                              void* d_out, int out_size) {
    const float* x    = (const float*)d_in[0];
    const int*   eidx = (const int*)d_in[1];
    const int*   eli  = (const int*)d_in[2];
    const float* W1   = (const float*)d_in[3];
    const float* as1  = (const float*)d_in[4];
    const float* ad1  = (const float*)d_in[5];
    const float* b1   = (const float*)d_in[6];
    const float* W2   = (const float*)d_in[7];
    const float* as2  = (const float*)d_in[8];
    const float* ad2  = (const float*)d_in[9];
    const float* b2   = (const float*)d_in[10];
    float* out = (float*)d_out;

    const int N  = in_sizes[0] / 128;
    const int E  = in_sizes[1] / 2;
    const int EL = in_sizes[2] / 2;
    const int* esrc = eidx;
    const int* edst = eidx + E;
    const int T = E + N;

    cudaFuncSetAttribute(gemm_alpha_kernel<128>, cudaFuncAttributeMaxDynamicSharedMemorySize, 131072);
    cudaFuncSetAttribute(gemm_alpha_kernel<64>,  cudaFuncAttributeMaxDynamicSharedMemorySize,  98304);

    void *ph1h, *pz1, *ph2;
    float *pas1, *pad1, *pas2, *pad2;
    cudaGetSymbolAddress(&ph1h, g_h1h);
    cudaGetSymbolAddress(&pz1,  g_z1);
    cudaGetSymbolAddress(&ph2,  g_h2);
    cudaGetSymbolAddress((void**)&pas1, g_as1);
    cudaGetSymbolAddress((void**)&pad1, g_ad1);
    cudaGetSymbolAddress((void**)&pas2, g_as2);
    cudaGetSymbolAddress((void**)&pad2, g_ad2);

    const int B = 256;
    auto cdiv = [](long long a, long long b) { return (int)((a + b - 1) / b); };
    const int nb = cdiv(N, 1024);

    // CSR structure
    zero_deg_kernel<<<cdiv(N, B), B>>>(N);
    hist_kernel<<<cdiv(T, B), B>>>(edst, E, N);
    scan1_kernel<<<nb, 1024>>>(N);
    scan2_kernel<<<1, 128>>>(nb);
    scan3_kernel<<<cdiv(N, B), B>>>(N, T);
    scatter_kernel<<<cdiv(T, B), B>>>(esrc, edst, E, N);

    // layer 1: GEMM + alpha fused
    gemm_alpha_kernel<128><<<cdiv(N, 128), 256, 131072>>>(x, W1, ph1h, as1, ad1, pas1, pad1, N);
    agg1_kernel<<<cdiv(N, 8), 256>>>(b1, N);

    // layer 2
    gemm_alpha_kernel<64><<<cdiv(N, 128), 256, 98304>>>((const float*)pz1, W2, ph2, as2, ad2, pas2, pad2, N);
    agg2_kernel<<<cdiv(N, 8), 256>>>(b2, N);

    // decode
    decode_kernel<<<cdiv((long long)EL * 16, B), B>>>(eli, EL, out);
}

// round 4
// speedup vs baseline: 1.2176x; 1.2176x over previous
#include <cuda_runtime.h>
#include <cuda_fp16.h>

#define MAXN 100000
#define MAXE 1600000
typedef unsigned long long u64;

// ---------------- scratch (device globals; allocation-free) ----------------
__device__ __align__(16) __half g_h1h[MAXN * 128];  // layer1 features (fp16, gather-only)
__device__ __align__(16) float g_z1[MAXN * 128];    // layer1 output z = elu(agg + b1)
__device__ __align__(16) float g_h2[MAXN * 64];     // layer2 features h2 = z@W2 (fp32)
__device__ __align__(16) float g_z2[MAXN * 64];     // layer2 output z2
__device__ __align__(8) float g_as1[MAXN * 2];
__device__ __align__(8) float g_ad1[MAXN * 2];
__device__ float g_as2[MAXN];
__device__ float g_ad2[MAXN];
__device__ int g_deg[MAXN];
__device__ int g_rowstart[MAXN + 1];
__device__ int g_cursor[MAXN];
__device__ int g_part[128];
__device__ int g_csr_src[MAXE + MAXN];

// ---------------- f32x2 packed helpers ----------------
__device__ __forceinline__ u64 pack2(float lo, float hi) {
    u64 r;
    asm("mov.b64 %0, {%1, %2};" : "=l"(r) : "f"(lo), "f"(hi));
    return r;
}
__device__ __forceinline__ void unpack2(u64 v, float& lo, float& hi) {
    asm("mov.b64 {%0, %1}, %2;" : "=f"(lo), "=f"(hi) : "l"(v));
}
__device__ __forceinline__ void fma2(u64& d, u64 a, u64 b) {
    asm("fma.rn.f32x2 %0, %1, %2, %0;" : "+l"(d) : "l"(a), "l"(b));
}

// ---------------- CSR build ----------------
__global__ void zero_deg_kernel(int N) {
    int i = blockIdx.x * blockDim.x + threadIdx.x;
    if (i < N) g_deg[i] = 0;
}

__global__ void hist_kernel(const int* __restrict__ edst, int E, int N) {
    int t = blockIdx.x * blockDim.x + threadIdx.x;
    if (t >= E + N) return;
    int dst = (t < E) ? edst[t] : (t - E);
    atomicAdd(&g_deg[dst], 1);
}

__global__ void scan1_kernel(int N) {
    __shared__ int sm[1024];
    int i = blockIdx.x * 1024 + threadIdx.x;
    int v = (i < N) ? g_deg[i] : 0;
    sm[threadIdx.x] = v;
    __syncthreads();
#pragma unroll
    for (int o = 1; o < 1024; o <<= 1) {
        int t = 0;
        if (threadIdx.x >= o) t = sm[threadIdx.x - o];
        __syncthreads();
        if (threadIdx.x >= o) sm[threadIdx.x] += t;
        __syncthreads();
    }
    if (i < N) g_rowstart[i] = sm[threadIdx.x] - v;
    if (threadIdx.x == 1023) g_part[blockIdx.x] = sm[1023];
}

__global__ void scan2_kernel(int nb) {
    __shared__ int sm[128];
    int v = (threadIdx.x < nb) ? g_part[threadIdx.x] : 0;
    sm[threadIdx.x] = v;
    __syncthreads();
#pragma unroll
    for (int o = 1; o < 128; o <<= 1) {
        int t = 0;
        if (threadIdx.x >= o) t = sm[threadIdx.x - o];
        __syncthreads();
        if (threadIdx.x >= o) sm[threadIdx.x] += t;
        __syncthreads();
    }
    if (threadIdx.x < nb) g_part[threadIdx.x] = sm[threadIdx.x] - v;
}

__global__ void scan3_kernel(int N, int total) {
    int i = blockIdx.x * blockDim.x + threadIdx.x;
    if (i < N) {
        int v = g_rowstart[i] + g_part[i >> 10];
        g_rowstart[i] = v;
        g_cursor[i] = v;
    }
    if (i == 0) g_rowstart[N] = total;
}

__global__ void scatter_kernel(const int* __restrict__ esrc, const int* __restrict__ edst,
                               int E, int N) {
    int t = blockIdx.x * blockDim.x + threadIdx.x;
    if (t >= E + N) return;
    int src, dst;
    if (t < E) { src = esrc[t]; dst = edst[t]; }
    else       { src = dst = t - E; }
    int pos = atomicAdd(&g_cursor[dst], 1);
    g_csr_src[pos] = src;
}

// ------- fused GEMM + alpha: Y = X@W; as/ad = (Y*a_src).sum / (Y*a_dst).sum -------
// Register-lean epilogue: per-row unpack + shfl reduce (no smem, no atomics).
template <int NC>
__global__ void gemm_alpha_kernel(const float* __restrict__ X, const float* __restrict__ W,
                                  void* __restrict__ Yout,
                                  const float* __restrict__ av_s, const float* __restrict__ av_d,
                                  float* __restrict__ out_s, float* __restrict__ out_d, int N) {
    extern __shared__ float smem[];
    float* Xs = smem;               // 128 x 128
    float* Ws = smem + 128 * 128;   // 128 x NC
    const int tid = threadIdx.x;
    const int row0 = blockIdx.x * 128;
    constexpr int NH = (NC == 128) ? 2 : 1;

    for (int i = tid * 4; i < 128 * NC; i += 256 * 4)
        *(float4*)&Ws[i] = *(const float4*)&W[i];
    for (int i = tid * 4; i < 128 * 128; i += 256 * 4) {
        int gr = row0 + (i >> 7);
        float4 v = make_float4(0.f, 0.f, 0.f, 0.f);
        if (gr < N) v = *(const float4*)&X[gr * 128 + (i & 127)];
        *(float4*)&Xs[i] = v;
    }
    __syncthreads();

    constexpr int MC = NC / 16;   // 8 or 4
    constexpr int MH = MC / 2;
    const int tx = tid & 15, ty = tid >> 4;
    const int r0 = ty * 8, c0 = tx * MC;
    u64 acc[8][MH];
#pragma unroll
    for (int i = 0; i < 8; i++)
#pragma unroll
        for (int j = 0; j < MH; j++) acc[i][j] = pack2(0.f, 0.f);

#pragma unroll 4
    for (int k = 0; k < 128; k++) {
        float bb[MC];
#pragma unroll
        for (int j4 = 0; j4 < MC; j4 += 4)
            *(float4*)&bb[j4] = *(const float4*)&Ws[k * NC + c0 + j4];
        u64 bp[MH];
#pragma unroll
        for (int j = 0; j < MH; j++) bp[j] = pack2(bb[2 * j], bb[2 * j + 1]);
#pragma unroll
        for (int i = 0; i < 8; i++) {
            float a = Xs[(r0 + i) * 128 + k];
            u64 ap = pack2(a, a);
#pragma unroll
            for (int j = 0; j < MH; j++) fma2(acc[i][j], ap, bp[j]);
        }
    }

    // alpha vectors for this thread's columns
    float avs[MC], avd[MC];
#pragma unroll
    for (int j = 0; j < MC; j++) { avs[j] = av_s[c0 + j]; avd[j] = av_d[c0 + j]; }

    constexpr int RW = (NC == 128) ? 8 : 16;   // shfl reduce width over tx
    const int head = (NC == 128) ? (tx >> 3) : 0;

#pragma unroll
    for (int i = 0; i < 8; i++) {
        float t[MC];
#pragma unroll
        for (int j = 0; j < MH; j++) unpack2(acc[i][j], t[2 * j], t[2 * j + 1]);
        int gr = row0 + r0 + i;
        if (gr < N) {
            if (NC == 128) {
                __half hb[8];
#pragma unroll
                for (int j = 0; j < MC; j++) hb[j] = __float2half_rn(t[j]);
                *(uint4*)((__half*)Yout + (size_t)gr * 128 + c0) = *(uint4*)hb;
            } else {
#pragma unroll
                for (int j4 = 0; j4 < MC; j4 += 4)
                    *(float4*)((float*)Yout + (size_t)gr * 64 + c0 + j4) = *(float4*)&t[j4];
            }
        }
        float ps = 0.f, pd = 0.f;
#pragma unroll
        for (int j = 0; j < MC; j++) {
            ps = fmaf(t[j], avs[j], ps);
            pd = fmaf(t[j], avd[j], pd);
        }
#pragma unroll
        for (int o = RW / 2; o; o >>= 1) {
            ps += __shfl_down_sync(0xffffffffu, ps, o, RW);
            pd += __shfl_down_sync(0xffffffffu, pd, o, RW);
        }
        if ((tx & (RW - 1)) == 0 && gr < N) {
            out_s[gr * NH + head] = ps;
            out_d[gr * NH + head] = pd;
        }
    }
}

// ---------------- layer1 aggregate: warp/dst, 2 edges per iter, fp16 uint4 gather ----------------
__global__ void agg1_kernel(const float* __restrict__ b1, int N) {
    int w = blockIdx.x * 8 + (threadIdx.x >> 5);
    int lane = threadIdx.x & 31;
    if (w >= N) return;
    int s0 = g_rowstart[w], s1 = g_rowstart[w + 1];
    float2 ad = *(const float2*)&g_ad1[w * 2];
    const int half = lane >> 4;   // edge slot 0/1
    const int fl = lane & 15;     // feature lane: feats [8*fl, 8*fl+8)
    float acc[8];
#pragma unroll
    for (int k = 0; k < 8; k++) acc[k] = 0.f;
    float den0 = 0.f, den1 = 0.f;

    for (int base = s0; base < s1; base += 32) {
        int e = base + lane;
        int msrc = 0;
        float me0 = 0.f, me1 = 0.f;
        if (e < s1) {
            msrc = g_csr_src[e];
            float2 as = *(const float2*)&g_as1[msrc * 2];
            float v0 = as.x + ad.x, v1 = as.y + ad.y;
            v0 = v0 > 0.f ? v0 : 0.2f * v0;
            v1 = v1 > 0.f ? v1 : 0.2f * v1;
            me0 = __expf(v0);
            me1 = __expf(v1);
        }
        den0 += me0;
        den1 += me1;
        int cnt = min(32, s1 - base);
        for (int j = 0; j < cnt; j += 2) {
            int jj = j + half;
            bool valid = jj < cnt;
            int idx = valid ? jj : j;
            int s = __shfl_sync(0xffffffffu, msrc, idx);
            float a0 = __shfl_sync(0xffffffffu, me0, idx);
            float a1 = __shfl_sync(0xffffffffu, me1, idx);
            float a = (fl >= 8) ? a1 : a0;   // feats 0..63 head0, 64..127 head1
            if (!valid) a = 0.f;
            uint4 u = ((const uint4*)(g_h1h + (size_t)s * 128))[fl];
            __half2* ph = (__half2*)&u;
#pragma unroll
            for (int q = 0; q < 4; q++) {
                float2 f = __half22float2(ph[q]);
                acc[2 * q]     = fmaf(a, f.x, acc[2 * q]);
                acc[2 * q + 1] = fmaf(a, f.y, acc[2 * q + 1]);
            }
        }
    }
    // merge edge slots
#pragma unroll
    for (int k = 0; k < 8; k++) acc[k] += __shfl_xor_sync(0xffffffffu, acc[k], 16);
#pragma unroll
    for (int o = 16; o; o >>= 1) {
        den0 += __shfl_xor_sync(0xffffffffu, den0, o);
        den1 += __shfl_xor_sync(0xffffffffu, den1, o);
    }
    if (half == 0) {
        float rden = 1.f / ((fl >= 8) ? den1 : den0);
        float r[8];
#pragma unroll
        for (int k = 0; k < 8; k++) {
            float v = acc[k] * rden + b1[fl * 8 + k];
            r[k] = v > 0.f ? v : (__expf(v) - 1.f);
        }
        *(float4*)&g_z1[(size_t)w * 128 + fl * 8]     = *(float4*)&r[0];
        *(float4*)&g_z1[(size_t)w * 128 + fl * 8 + 4] = *(float4*)&r[4];
    }
}

// ---------------- layer2 aggregate: warp/dst, 2 edges per iter, float4 gather ----------------
__global__ void agg2_kernel(const float* __restrict__ b2, int N) {
    int w = blockIdx.x * 8 + (threadIdx.x >> 5);
    int lane = threadIdx.x & 31;
    if (w >= N) return;
    int s0 = g_rowstart[w], s1 = g_rowstart[w + 1];
    float add_d = g_ad2[w];
    const int half = lane >> 4;
    const int fl = lane & 15;     // feats [4*fl, 4*fl+4)
    float4 acc = make_float4(0.f, 0.f, 0.f, 0.f);
    float den = 0.f;

    for (int base = s0; base < s1; base += 32) {
        int e = base + lane;
        int msrc = 0;
        float mee = 0.f;
        if (e < s1) {
            msrc = g_csr_src[e];
            float v = g_as2[msrc] + add_d;
            v = v > 0.f ? v : 0.2f * v;
            mee = __expf(v);
        }
        den += mee;
        int cnt = min(32, s1 - base);
        for (int j = 0; j < cnt; j += 2) {
            int jj = j + half;
            bool valid = jj < cnt;
            int idx = valid ? jj : j;
            int s = __shfl_sync(0xffffffffu, msrc, idx);
            float a = __shfl_sync(0xffffffffu, mee, idx);
            if (!valid) a = 0.f;
            float4 v = ((const float4*)(g_h2 + (size_t)s * 64))[fl];
            acc.x = fmaf(a, v.x, acc.x);
            acc.y = fmaf(a, v.y, acc.y);
            acc.z = fmaf(a, v.z, acc.z);
            acc.w = fmaf(a, v.w, acc.w);
        }
    }
    acc.x += __shfl_xor_sync(0xffffffffu, acc.x, 16);
    acc.y += __shfl_xor_sync(0xffffffffu, acc.y, 16);
    acc.z += __shfl_xor_sync(0xffffffffu, acc.z, 16);
    acc.w += __shfl_xor_sync(0xffffffffu, acc.w, 16);
#pragma unroll
    for (int o = 16; o; o >>= 1) den += __shfl_xor_sync(0xffffffffu, den, o);
    if (half == 0) {
        float rden = 1.f / den;
        float4 b = *(const float4*)&b2[fl * 4];
        float4 r;
        r.x = acc.x * rden + b.x;
        r.y = acc.y * rden + b.y;
        r.z = acc.z * rden + b.z;
        r.w = acc.w * rden + b.w;
        *(float4*)&g_z2[(size_t)w * 64 + fl * 4] = r;
    }
}

// ---------------- decode: dot(z2[a], z2[b]) over 64 ----------------
__global__ void decode_kernel(const int* __restrict__ eli, int EL, float* __restrict__ out) {
    int t = blockIdx.x * blockDim.x + threadIdx.x;
    int g = t >> 4, li = t & 15;
    if (g >= EL) return;
    int a = eli[g];
    int b = eli[EL + g];
    float4 va = *(const float4*)&g_z2[(size_t)a * 64 + li * 4];
    float4 vb = *(const float4*)&g_z2[(size_t)b * 64 + li * 4];
    float s = va.x * vb.x + va.y * vb.y + va.z * vb.z + va.w * vb.w;
#pragma unroll
    for (int o = 8; o; o >>= 1) s += __shfl_down_sync(0xffffffffu, s, o, 16);
    if (li == 0) out[g] = s;
}

// ---------------- launcher ----------------
extern "C" void kernel_launch(void* const* d_in, const int* in_sizes, int n_in,
                              void* d_out, int out_size) {
    const float* x    = (const float*)d_in[0];
    const int*   eidx = (const int*)d_in[1];
    const int*   eli  = (const int*)d_in[2];
    const float* W1   = (const float*)d_in[3];
    const float* as1  = (const float*)d_in[4];
    const float* ad1  = (const float*)d_in[5];
    const float* b1   = (const float*)d_in[6];
    const float* W2   = (const float*)d_in[7];
    const float* as2  = (const float*)d_in[8];
    const float* ad2  = (const float*)d_in[9];
    const float* b2   = (const float*)d_in[10];
    float* out = (float*)d_out;

    const int N  = in_sizes[0] / 128;
    const int E  = in_sizes[1] / 2;
    const int EL = in_sizes[2] / 2;
    const int* esrc = eidx;
    const int* edst = eidx + E;
    const int T = E + N;

    cudaFuncSetAttribute(gemm_alpha_kernel<128>, cudaFuncAttributeMaxDynamicSharedMemorySize, 131072);
    cudaFuncSetAttribute(gemm_alpha_kernel<64>,  cudaFuncAttributeMaxDynamicSharedMemorySize,  98304);

    void *ph1h, *pz1, *ph2;
    float *pas1, *pad1, *pas2, *pad2;
    cudaGetSymbolAddress(&ph1h, g_h1h);
    cudaGetSymbolAddress(&pz1,  g_z1);
    cudaGetSymbolAddress(&ph2,  g_h2);
    cudaGetSymbolAddress((void**)&pas1, g_as1);
    cudaGetSymbolAddress((void**)&pad1, g_ad1);
    cudaGetSymbolAddress((void**)&pas2, g_as2);
    cudaGetSymbolAddress((void**)&pad2, g_ad2);

    const int B = 256;
    auto cdiv = [](long long a, long long b) { return (int)((a + b - 1) / b); };
    const int nb = cdiv(N, 1024);

    // CSR structure
    zero_deg_kernel<<<cdiv(N, B), B>>>(N);
    hist_kernel<<<cdiv(T, B), B>>>(edst, E, N);
    scan1_kernel<<<nb, 1024>>>(N);
    scan2_kernel<<<1, 128>>>(nb);
    scan3_kernel<<<cdiv(N, B), B>>>(N, T);
    scatter_kernel<<<cdiv(T, B), B>>>(esrc, edst, E, N);

    // layer 1: GEMM + alpha fused
    gemm_alpha_kernel<128><<<cdiv(N, 128), 256, 131072>>>(x, W1, ph1h, as1, ad1, pas1, pad1, N);
    agg1_kernel<<<cdiv(N, 8), 256>>>(b1, N);

    // layer 2
    gemm_alpha_kernel<64><<<cdiv(N, 128), 256, 98304>>>((const float*)pz1, W2, ph2, as2, ad2, pas2, pad2, N);
    agg2_kernel<<<cdiv(N, 8), 256>>>(b2, N);

    // decode
    decode_kernel<<<cdiv((long long)EL * 16, B), B>>>(eli, EL, out);
}

// round 5
// speedup vs baseline: 1.8226x; 1.4969x over previous
#include <cuda_runtime.h>
#include <cuda_fp16.h>
#include <cstdint>

#define MAXN 100000
#define MAXE 1600000

// ---------------- scratch (device globals; allocation-free) ----------------
__device__ __align__(16) __half g_h1h[MAXN * 128];  // layer1 features (fp16)
__device__ __align__(16) float g_z1[MAXN * 128];    // layer1 output z = elu(agg + b1)
__device__ __align__(16) __half g_h2h[MAXN * 64];   // layer2 features (fp16)
__device__ __align__(16) float g_z2[MAXN * 64];     // layer2 output z2 (fp32)
__device__ __align__(8) float g_as1[MAXN * 2];
__device__ __align__(8) float g_ad1[MAXN * 2];
__device__ float g_as2[MAXN];
__device__ float g_ad2[MAXN];
__device__ int g_deg[MAXN];
__device__ int g_rowstart[MAXN + 1];
__device__ int g_cursor[MAXN];
__device__ int g_part[256];
__device__ int g_csr_src[MAXE + MAXN];

// ---------------- mma helpers ----------------
__device__ __forceinline__ uint32_t smem_u32(const void* p) {
    uint32_t a;
    asm("{ .reg .u64 t; cvta.to.shared.u64 t, %1; cvt.u32.u64 %0, t; }" : "=r"(a) : "l"(p));
    return a;
}
__device__ __forceinline__ void ldsm4(uint32_t& r0, uint32_t& r1, uint32_t& r2, uint32_t& r3,
                                      uint32_t addr) {
    asm volatile("ldmatrix.sync.aligned.m8n8.x4.shared.b16 {%0,%1,%2,%3}, [%4];"
                 : "=r"(r0), "=r"(r1), "=r"(r2), "=r"(r3) : "r"(addr));
}
__device__ __forceinline__ void ldsm4t(uint32_t& r0, uint32_t& r1, uint32_t& r2, uint32_t& r3,
                                       uint32_t addr) {
    asm volatile("ldmatrix.sync.aligned.m8n8.x4.trans.shared.b16 {%0,%1,%2,%3}, [%4];"
                 : "=r"(r0), "=r"(r1), "=r"(r2), "=r"(r3) : "r"(addr));
}
__device__ __forceinline__ void mma16816(float* c, const uint32_t* a, const uint32_t* b) {
    asm volatile(
        "mma.sync.aligned.m16n8k16.row.col.f32.f16.f16.f32 "
        "{%0,%1,%2,%3}, {%4,%5,%6,%7}, {%8,%9}, {%0,%1,%2,%3};"
        : "+f"(c[0]), "+f"(c[1]), "+f"(c[2]), "+f"(c[3])
        : "r"(a[0]), "r"(a[1]), "r"(a[2]), "r"(a[3]), "r"(b[0]), "r"(b[1]));
}

// ---------------- CSR build ----------------
__global__ void zero_deg_kernel(int N) {
    int i = blockIdx.x * blockDim.x + threadIdx.x;
    if (i < N) g_deg[i] = 0;
}

__global__ void hist_kernel(const int* __restrict__ edst, int E, int N) {
    int t = blockIdx.x * blockDim.x + threadIdx.x;
    if (t >= E + N) return;
    int dst = (t < E) ? edst[t] : (t - E);
    atomicAdd(&g_deg[dst], 1);
}

__global__ void scan1_kernel(int N) {
    __shared__ int sm[1024];
    int i = blockIdx.x * 1024 + threadIdx.x;
    int v = (i < N) ? g_deg[i] : 0;
    sm[threadIdx.x] = v;
    __syncthreads();
#pragma unroll
    for (int o = 1; o < 1024; o <<= 1) {
        int t = 0;
        if (threadIdx.x >= o) t = sm[threadIdx.x - o];
        __syncthreads();
        if (threadIdx.x >= o) sm[threadIdx.x] += t;
        __syncthreads();
    }
    if (i < N) g_rowstart[i] = sm[threadIdx.x] - v;
    if (threadIdx.x == 1023) g_part[blockIdx.x] = sm[1023];
}

// scan of partials (<=256) done redundantly per block, fused with rowstart fixup
__global__ void scan3_kernel(int N, int total, int nb) {
    __shared__ int sp[256];
    int tid = threadIdx.x;
    int pv = (tid < nb) ? g_part[tid] : 0;
    sp[tid] = pv;
    __syncthreads();
#pragma unroll
    for (int o = 1; o < 256; o <<= 1) {
        int t = 0;
        if (tid >= o) t = sp[tid - o];
        __syncthreads();
        if (tid >= o) sp[tid] += t;
        __syncthreads();
    }
    // exclusive offset for block b = sp[b] - part[b]
    int i = blockIdx.x * blockDim.x + tid;
    if (i < N) {
        int b = i >> 10;
        int v = g_rowstart[i] + sp[b] - ((b < nb) ? g_part[b] : 0);
        // note: need original part[b]; recompute via subtraction of own pv only valid for b==tid.
        g_rowstart[i] = v;
        g_cursor[i] = v;
    }
    if (i == 0) g_rowstart[N] = total;
}

__global__ void scatter_kernel(const int* __restrict__ esrc, const int* __restrict__ edst,
                               int E, int N) {
    int t = blockIdx.x * blockDim.x + threadIdx.x;
    if (t >= E + N) return;
    int src, dst;
    if (t < E) { src = esrc[t]; dst = edst[t]; }
    else       { src = dst = t - E; }
    int pos = atomicAdd(&g_cursor[dst], 1);
    g_csr_src[pos] = src;
}

// ------- tensor-core GEMM + alpha: Y(fp16) = X(fp32->fp16) @ W(fp32->fp16) -------
// 256 threads; block tile 128 x NC, K=128 fully in smem. Warp grid 4x2.
template <int NC>
__global__ void __launch_bounds__(256, 2)
mma_gemm_alpha_kernel(const float* __restrict__ X, const float* __restrict__ W,
                      __half* __restrict__ Y,
                      const float* __restrict__ av_s, const float* __restrict__ av_d,
                      float* __restrict__ out_s, float* __restrict__ out_d, int N) {
    extern __shared__ __half hsm[];
    constexpr int LDA = 136;        // 128 + 8 pad (halves)
    constexpr int LDB = NC + 8;
    __half* As = hsm;                         // 128 x LDA
    __half* Bs = hsm + 128 * LDA;             // 128 x LDB
    const int tid = threadIdx.x;
    const int row0 = blockIdx.x * 128;
    constexpr int NH = (NC == 128) ? 2 : 1;
    constexpr int NT = NC / 16;               // n8-tiles per warp (8 or 4)

    // stage A (fp32 -> fp16)
    for (int i = tid * 4; i < 128 * 128; i += 1024) {
        int r = i >> 7, c = i & 127;
        int gr = row0 + r;
        float4 v = make_float4(0.f, 0.f, 0.f, 0.f);
        if (gr < N) v = *(const float4*)&X[(size_t)gr * 128 + c];
        __half2 h0 = __floats2half2_rn(v.x, v.y);
        __half2 h1 = __floats2half2_rn(v.z, v.w);
        uint2 pk = make_uint2(*(uint32_t*)&h0, *(uint32_t*)&h1);
        *(uint2*)&As[r * LDA + c] = pk;
    }
    // stage B (fp32 -> fp16), W is [128][NC]
    for (int i = tid * 4; i < 128 * NC; i += 1024) {
        int r = i / NC, c = i % NC;
        float4 v = *(const float4*)&W[i];
        __half2 h0 = __floats2half2_rn(v.x, v.y);
        __half2 h1 = __floats2half2_rn(v.z, v.w);
        uint2 pk = make_uint2(*(uint32_t*)&h0, *(uint32_t*)&h1);
        *(uint2*)&Bs[r * LDB + c] = pk;
    }
    __syncthreads();

    const int lane = tid & 31, wid = tid >> 5;
    const int wr = wid >> 1, wc = wid & 1;
    const int r_base = wr * 32;
    const int c_base = wc * (NC / 2);

    float c[2][NT][4];
#pragma unroll
    for (int mt = 0; mt < 2; mt++)
#pragma unroll
        for (int nt = 0; nt < NT; nt++)
#pragma unroll
            for (int q = 0; q < 4; q++) c[mt][nt][q] = 0.f;

    const uint32_t a_base = smem_u32(As);
    const uint32_t b_base = smem_u32(Bs);
    const int lr = lane & 15, lh = lane >> 4;

#pragma unroll
    for (int kk = 0; kk < 8; kk++) {
        int k0 = kk * 16;
        uint32_t a[2][4];
#pragma unroll
        for (int mt = 0; mt < 2; mt++) {
            uint32_t addr = a_base + ((r_base + mt * 16 + lr) * LDA + k0 + lh * 8) * 2;
            ldsm4(a[mt][0], a[mt][1], a[mt][2], a[mt][3], addr);
        }
        uint32_t b[NT][2];
#pragma unroll
        for (int nt2 = 0; nt2 < NT / 2; nt2++) {
            int n0 = c_base + nt2 * 16;
            uint32_t addr = b_base + ((k0 + lr) * LDB + n0 + lh * 8) * 2;
            uint32_t r0, r1, r2, r3;
            ldsm4t(r0, r1, r2, r3, addr);
            b[2 * nt2][0] = r0; b[2 * nt2][1] = r1;
            b[2 * nt2 + 1][0] = r2; b[2 * nt2 + 1][1] = r3;
        }
#pragma unroll
        for (int mt = 0; mt < 2; mt++)
#pragma unroll
            for (int nt = 0; nt < NT; nt++) mma16816(c[mt][nt], a[mt], b[nt]);
    }

    // epilogue: write Y (fp16) + alpha partials
    const int row_in = lane >> 2;      // 0..7
    const int qc = (lane & 3) * 2;
    float psr[2][2], pdr[2][2];
#pragma unroll
    for (int mt = 0; mt < 2; mt++) {
        float ps0 = 0.f, pd0 = 0.f, ps1 = 0.f, pd1 = 0.f;
        int lr0 = r_base + mt * 16 + row_in;
        int gr0 = row0 + lr0, gr1 = gr0 + 8;
#pragma unroll
        for (int nt = 0; nt < NT; nt++) {
            int col = c_base + nt * 8 + qc;
            float avs0 = av_s[col], avs1 = av_s[col + 1];
            float avd0 = av_d[col], avd1 = av_d[col + 1];
            float* cc = c[mt][nt];
            ps0 = fmaf(cc[0], avs0, fmaf(cc[1], avs1, ps0));
            pd0 = fmaf(cc[0], avd0, fmaf(cc[1], avd1, pd0));
            ps1 = fmaf(cc[2], avs0, fmaf(cc[3], avs1, ps1));
            pd1 = fmaf(cc[2], avd0, fmaf(cc[3], avd1, pd1));
            if (gr0 < N) *(__half2*)&Y[(size_t)gr0 * NC + col] = __floats2half2_rn(cc[0], cc[1]);
            if (gr1 < N) *(__half2*)&Y[(size_t)gr1 * NC + col] = __floats2half2_rn(cc[2], cc[3]);
        }
#pragma unroll
        for (int o = 1; o <= 2; o <<= 1) {
            ps0 += __shfl_xor_sync(0xffffffffu, ps0, o);
            pd0 += __shfl_xor_sync(0xffffffffu, pd0, o);
            ps1 += __shfl_xor_sync(0xffffffffu, ps1, o);
            pd1 += __shfl_xor_sync(0xffffffffu, pd1, o);
        }
        psr[mt][0] = ps0; psr[mt][1] = ps1;
        pdr[mt][0] = pd0; pdr[mt][1] = pd1;
    }

    if (NC == 128) {
        // warp col == head; rows unique per warp -> direct store
        if ((lane & 3) == 0) {
#pragma unroll
            for (int mt = 0; mt < 2; mt++) {
                int gr0 = row0 + r_base + mt * 16 + row_in;
#pragma unroll
                for (int hh = 0; hh < 2; hh++) {
                    int gr = gr0 + hh * 8;
                    if (gr < N) {
                        out_s[(size_t)gr * NH + wc] = psr[mt][hh];
                        out_d[(size_t)gr * NH + wc] = pdr[mt][hh];
                    }
                }
            }
        }
    } else {
        // two warp-cols share rows -> smem reduce
        __syncthreads();
        float* sS = (float*)hsm;
        float* sD = sS + 128;
        if (tid < 128) { sS[tid] = 0.f; sD[tid] = 0.f; }
        __syncthreads();
        if ((lane & 3) == 0) {
#pragma unroll
            for (int mt = 0; mt < 2; mt++) {
                int lr0 = r_base + mt * 16 + row_in;
#pragma unroll
                for (int hh = 0; hh < 2; hh++) {
                    atomicAdd(&sS[lr0 + hh * 8], psr[mt][hh]);
                    atomicAdd(&sD[lr0 + hh * 8], pdr[mt][hh]);
                }
            }
        }
        __syncthreads();
        if (tid < 128) {
            int gr = row0 + tid;
            if (gr < N) {
                out_s[gr] = sS[tid];
                out_d[gr] = sD[tid];
            }
        }
    }
}

// ---------------- layer1 aggregate: warp/dst, 8 edges per unrolled iter, fp16 gather ----------------
__global__ void agg1_kernel(const float* __restrict__ b1, int N) {
    int w = blockIdx.x * 8 + (threadIdx.x >> 5);
    int lane = threadIdx.x & 31;
    if (w >= N) return;
    int s0 = g_rowstart[w], s1 = g_rowstart[w + 1];
    float2 ad = *(const float2*)&g_ad1[w * 2];
    const int half = lane >> 4;
    const int fl = lane & 15;   // feats [8*fl, 8*fl+8)
    float acc[8];
#pragma unroll
    for (int k = 0; k < 8; k++) acc[k] = 0.f;
    float den0 = 0.f, den1 = 0.f;

    for (int base = s0; base < s1; base += 32) {
        int e = base + lane;
        int msrc = 0;
        float me0 = 0.f, me1 = 0.f;
        if (e < s1) {
            msrc = g_csr_src[e];
            float2 as = *(const float2*)&g_as1[msrc * 2];
            float v0 = as.x + ad.x, v1 = as.y + ad.y;
            v0 = v0 > 0.f ? v0 : 0.2f * v0;
            v1 = v1 > 0.f ? v1 : 0.2f * v1;
            me0 = __expf(v0);
            me1 = __expf(v1);
        }
        den0 += me0;
        den1 += me1;
        int cnt = min(32, s1 - base);
        int j = 0;
        for (; j + 8 <= cnt; j += 8) {
            int sq[4]; float aq[4]; uint4 uq[4];
#pragma unroll
            for (int q = 0; q < 4; q++) {
                int idx = j + 2 * q + half;
                sq[q] = __shfl_sync(0xffffffffu, msrc, idx);
                float a0 = __shfl_sync(0xffffffffu, me0, idx);
                float a1 = __shfl_sync(0xffffffffu, me1, idx);
                aq[q] = (fl >= 8) ? a1 : a0;
            }
#pragma unroll
            for (int q = 0; q < 4; q++)
                uq[q] = ((const uint4*)(g_h1h + (size_t)sq[q] * 128))[fl];
#pragma unroll
            for (int q = 0; q < 4; q++) {
                __half2* ph = (__half2*)&uq[q];
#pragma unroll
                for (int p = 0; p < 4; p++) {
                    float2 f = __half22float2(ph[p]);
                    acc[2 * p]     = fmaf(aq[q], f.x, acc[2 * p]);
                    acc[2 * p + 1] = fmaf(aq[q], f.y, acc[2 * p + 1]);
                }
            }
        }
        for (; j < cnt; j += 2) {
            int jj = j + half;
            bool valid = jj < cnt;
            int idx = valid ? jj : j;
            int s = __shfl_sync(0xffffffffu, msrc, idx);
            float a0 = __shfl_sync(0xffffffffu, me0, idx);
            float a1 = __shfl_sync(0xffffffffu, me1, idx);
            float a = (fl >= 8) ? a1 : a0;
            if (!valid) a = 0.f;
            uint4 u = ((const uint4*)(g_h1h + (size_t)s * 128))[fl];
            __half2* ph = (__half2*)&u;
#pragma unroll
            for (int p = 0; p < 4; p++) {
                float2 f = __half22float2(ph[p]);
                acc[2 * p]     = fmaf(a, f.x, acc[2 * p]);
                acc[2 * p + 1] = fmaf(a, f.y, acc[2 * p + 1]);
            }
        }
    }
#pragma unroll
    for (int k = 0; k < 8; k++) acc[k] += __shfl_xor_sync(0xffffffffu, acc[k], 16);
#pragma unroll
    for (int o = 16; o; o >>= 1) {
        den0 += __shfl_xor_sync(0xffffffffu, den0, o);
        den1 += __shfl_xor_sync(0xffffffffu, den1, o);
    }
    if (half == 0) {
        float rden = 1.f / ((fl >= 8) ? den1 : den0);
        float r[8];
#pragma unroll
        for (int k = 0; k < 8; k++) {
            float v = acc[k] * rden + b1[fl * 8 + k];
            r[k] = v > 0.f ? v : (__expf(v) - 1.f);
        }
        *(float4*)&g_z1[(size_t)w * 128 + fl * 8]     = *(float4*)&r[0];
        *(float4*)&g_z1[(size_t)w * 128 + fl * 8 + 4] = *(float4*)&r[4];
    }
}

// ---------------- layer2 aggregate: warp/dst, 8 edges per unrolled iter, fp16 gather ----------------
__global__ void agg2_kernel(const float* __restrict__ b2, int N) {
    int w = blockIdx.x * 8 + (threadIdx.x >> 5);
    int lane = threadIdx.x & 31;
    if (w >= N) return;
    int s0 = g_rowstart[w], s1 = g_rowstart[w + 1];
    float add_d = g_ad2[w];
    const int half = lane >> 4;
    const int fl = lane & 15;   // feats [4*fl, 4*fl+4)
    float4 acc = make_float4(0.f, 0.f, 0.f, 0.f);
    float den = 0.f;

    for (int base = s0; base < s1; base += 32) {
        int e = base + lane;
        int msrc = 0;
        float mee = 0.f;
        if (e < s1) {
            msrc = g_csr_src[e];
            float v = g_as2[msrc] + add_d;
            v = v > 0.f ? v : 0.2f * v;
            mee = __expf(v);
        }
        den += mee;
        int cnt = min(32, s1 - base);
        int j = 0;
        for (; j + 8 <= cnt; j += 8) {
            int sq[4]; float aq[4]; uint2 uq[4];
#pragma unroll
            for (int q = 0; q < 4; q++) {
                int idx = j + 2 * q + half;
                sq[q] = __shfl_sync(0xffffffffu, msrc, idx);
                aq[q] = __shfl_sync(0xffffffffu, mee, idx);
            }
#pragma unroll
            for (int q = 0; q < 4; q++)
                uq[q] = ((const uint2*)(g_h2h + (size_t)sq[q] * 64))[fl];
#pragma unroll
            for (int q = 0; q < 4; q++) {
                __half2* ph = (__half2*)&uq[q];
                float2 f0 = __half22float2(ph[0]);
                float2 f1 = __half22float2(ph[1]);
                acc.x = fmaf(aq[q], f0.x, acc.x);
                acc.y = fmaf(aq[q], f0.y, acc.y);
                acc.z = fmaf(aq[q], f1.x, acc.z);
                acc.w = fmaf(aq[q], f1.y, acc.w);
            }
        }
        for (; j < cnt; j += 2) {
            int jj = j + half;
            bool valid = jj < cnt;
            int idx = valid ? jj : j;
            int s = __shfl_sync(0xffffffffu, msrc, idx);
            float a = __shfl_sync(0xffffffffu, mee, idx);
            if (!valid) a = 0.f;
            uint2 u = ((const uint2*)(g_h2h + (size_t)s * 64))[fl];
            __half2* ph = (__half2*)&u;
            float2 f0 = __half22float2(ph[0]);
            float2 f1 = __half22float2(ph[1]);
            acc.x = fmaf(a, f0.x, acc.x);
            acc.y = fmaf(a, f0.y, acc.y);
            acc.z = fmaf(a, f1.x, acc.z);
            acc.w = fmaf(a, f1.y, acc.w);
        }
    }
    acc.x += __shfl_xor_sync(0xffffffffu, acc.x, 16);
    acc.y += __shfl_xor_sync(0xffffffffu, acc.y, 16);
    acc.z += __shfl_xor_sync(0xffffffffu, acc.z, 16);
    acc.w += __shfl_xor_sync(0xffffffffu, acc.w, 16);
#pragma unroll
    for (int o = 16; o; o >>= 1) den += __shfl_xor_sync(0xffffffffu, den, o);
    if (half == 0) {
        float rden = 1.f / den;
        float4 b = *(const float4*)&b2[fl * 4];
        float4 r;
        r.x = acc.x * rden + b.x;
        r.y = acc.y * rden + b.y;
        r.z = acc.z * rden + b.z;
        r.w = acc.w * rden + b.w;
        *(float4*)&g_z2[(size_t)w * 64 + fl * 4] = r;
    }
}

// ---------------- decode: dot(z2[a], z2[b]) over 64 ----------------
__global__ void decode_kernel(const int* __restrict__ eli, int EL, float* __restrict__ out) {
    int t = blockIdx.x * blockDim.x + threadIdx.x;
    int g = t >> 4, li = t & 15;
    if (g >= EL) return;
    int a = eli[g];
    int b = eli[EL + g];
    float4 va = *(const float4*)&g_z2[(size_t)a * 64 + li * 4];
    float4 vb = *(const float4*)&g_z2[(size_t)b * 64 + li * 4];
    float s = va.x * vb.x + va.y * vb.y + va.z * vb.z + va.w * vb.w;
#pragma unroll
    for (int o = 8; o; o >>= 1) s += __shfl_down_sync(0xffffffffu, s, o, 16);
    if (li == 0) out[g] = s;
}

// ---------------- launcher ----------------
extern "C" void kernel_launch(void* const* d_in, const int* in_sizes, int n_in,
                              void* d_out, int out_size) {
    const float* x    = (const float*)d_in[0];
    const int*   eidx = (const int*)d_in[1];
    const int*   eli  = (const int*)d_in[2];
    const float* W1   = (const float*)d_in[3];
    const float* as1  = (const float*)d_in[4];
    const float* ad1  = (const float*)d_in[5];
    const float* b1   = (const float*)d_in[6];
    const float* W2   = (const float*)d_in[7];
    const float* as2  = (const float*)d_in[8];
    const float* ad2  = (const float*)d_in[9];
    const float* b2   = (const float*)d_in[10];
    float* out = (float*)d_out;

    const int N  = in_sizes[0] / 128;
    const int E  = in_sizes[1] / 2;
    const int EL = in_sizes[2] / 2;
    const int* esrc = eidx;
    const int* edst = eidx + E;
    const int T = E + N;

    const int SM1 = (128 * 136 + 128 * 136) * 2;  // 69632
    const int SM2 = (128 * 136 + 128 * 72) * 2;   // 53248
    cudaFuncSetAttribute(mma_gemm_alpha_kernel<128>, cudaFuncAttributeMaxDynamicSharedMemorySize, SM1);
    cudaFuncSetAttribute(mma_gemm_alpha_kernel<64>,  cudaFuncAttributeMaxDynamicSharedMemorySize, SM2);

    void *ph1h, *pz1, *ph2h;
    float *pas1, *pad1, *pas2, *pad2;
    cudaGetSymbolAddress(&ph1h, g_h1h);
    cudaGetSymbolAddress(&pz1,  g_z1);
    cudaGetSymbolAddress(&ph2h, g_h2h);
    cudaGetSymbolAddress((void**)&pas1, g_as1);
    cudaGetSymbolAddress((void**)&pad1, g_ad1);
    cudaGetSymbolAddress((void**)&pas2, g_as2);
    cudaGetSymbolAddress((void**)&pad2, g_ad2);

    const int B = 256;
    auto cdiv = [](long long a, long long b) { return (int)((a + b - 1) / b); };
    const int nb = cdiv(N, 1024);

    // CSR structure
    zero_deg_kernel<<<cdiv(N, B), B>>>(N);
    hist_kernel<<<cdiv(T, B), B>>>(edst, E, N);
    scan1_kernel<<<nb, 1024>>>(N);
    scan3_kernel<<<cdiv(N, B), B>>>(N, T, nb);
    scatter_kernel<<<cdiv(T, B), B>>>(esrc, edst, E, N);

    // layer 1
    mma_gemm_alpha_kernel<128><<<cdiv(N, 128), 256, SM1>>>(x, W1, (__half*)ph1h, as1, ad1, pas1, pad1, N);
    agg1_kernel<<<cdiv(N, 8), 256>>>(b1, N);

    // layer 2
    mma_gemm_alpha_kernel<64><<<cdiv(N, 128), 256, SM2>>>((const float*)pz1, W2, (__half*)ph2h, as2, ad2, pas2, pad2, N);
    agg2_kernel<<<cdiv(N, 8), 256>>>(b2, N);

    // decode
    decode_kernel<<<cdiv((long long)EL * 16, B), B>>>(eli, EL, out);
}